// round 15
// baseline (speedup 1.0000x reference)
#include <cuda_runtime.h>
#include <cuda_fp16.h>
#include <cstdint>
#include <cstddef>

#define DINL __device__ __forceinline__

// ---------------------------------------------------------------------------
// Scratch (device globals; no allocation allowed)
// Packed layout for all fp16 GEMM operands: 16 KB tiles of (128 rows x 64 k),
// row-major over (rowtile, ktile), interior pre-swizzled for ldmatrix.
// ---------------------------------------------------------------------------
__device__ float g_bcomb[1024];
__device__ float g_h2[32u * 1024u * 1024u];     // [B*T, H] fp32 (134 MB)
__device__ float g_pooled8[8 * 32 * 1024];      // per-segment partial pools
__device__ __align__(128) __half g_xhi[32u * 1024u * 1024u];
__device__ __align__(128) __half g_xlo[32u * 1024u * 1024u];
__device__ __align__(128) __half g_whi[1024u * 1024u];
__device__ __align__(128) __half g_wlo[1024u * 1024u];
__device__ __align__(128) __half g_ahi[1024u * 1024u];   // W_hid split
__device__ __align__(128) __half g_alo[1024u * 1024u];
__device__ __align__(128) __half g_bthi[1024u * 1024u];  // W_projT split
__device__ __align__(128) __half g_btlo[1024u * 1024u];

// Residual scale: lo' = (x - hi) * 2^12, combined as acc1 + acc2 * 2^-12.
static constexpr float LO_SCALE = 4096.0f;
static constexpr float LO_INV   = 1.0f / 4096.0f;

// ---------------------------------------------------------------------------
// PTX helpers (compute_103 baseline-safe)
// ---------------------------------------------------------------------------
DINL uint32_t smem_u32(const void* p) {
    uint32_t r;
    asm("{ .reg .u64 t; cvta.to.shared.u64 t, %1; cvt.u32.u64 %0, t; }"
        : "=r"(r) : "l"(p));
    return r;
}
DINL void cp16(uint32_t dst, const void* src) {
    asm volatile("cp.async.cg.shared.global [%0], [%1], 16;"
                 :: "r"(dst), "l"(src) : "memory");
}
DINL void cp_commit() { asm volatile("cp.async.commit_group;" ::: "memory"); }
template <int N> DINL void cp_wait() {
    asm volatile("cp.async.wait_group %0;" :: "n"(N) : "memory");
}
DINL void ldsm_x4(uint32_t* r, uint32_t addr) {
    asm volatile("ldmatrix.sync.aligned.m8n8.x4.shared.b16 {%0,%1,%2,%3}, [%4];"
                 : "=r"(r[0]), "=r"(r[1]), "=r"(r[2]), "=r"(r[3]) : "r"(addr));
}
DINL void mma_f16(float* d, const uint32_t* a, const uint32_t* b) {
    asm volatile(
        "mma.sync.aligned.m16n8k16.row.col.f32.f16.f16.f32 "
        "{%0,%1,%2,%3}, {%4,%5,%6,%7}, {%8,%9}, {%0,%1,%2,%3};"
        : "+f"(d[0]), "+f"(d[1]), "+f"(d[2]), "+f"(d[3])
        : "r"(a[0]), "r"(a[1]), "r"(a[2]), "r"(a[3]), "r"(b[0]), "r"(b[1]));
}
DINL void mbar_init(uint32_t addr, uint32_t cnt) {
    asm volatile("mbarrier.init.shared.b64 [%0], %1;" :: "r"(addr), "r"(cnt) : "memory");
}
DINL void mbar_expect_tx(uint32_t addr, uint32_t bytes) {
    asm volatile("mbarrier.arrive.expect_tx.shared.b64 _, [%0], %1;"
                 :: "r"(addr), "r"(bytes) : "memory");
}
DINL void mbar_arrive(uint32_t addr) {
    asm volatile("mbarrier.arrive.shared.b64 _, [%0];" :: "r"(addr) : "memory");
}
DINL void mbar_wait(uint32_t addr, uint32_t parity) {
    asm volatile(
        "{\n\t.reg .pred P;\n"
        "W1_%=:\n\tmbarrier.try_wait.parity.acquire.cta.shared::cta.b64 P, [%0], %1, 0x989680;\n\t"
        "@P bra W2_%=;\n\tbra W1_%=;\nW2_%=:\n\t}"
        :: "r"(addr), "r"(parity) : "memory");
}
// 1D bulk async copy global->smem, completion via mbarrier complete_tx.
DINL void bulk_g2s(uint32_t dst, const void* src, uint32_t bytes, uint32_t bar) {
    asm volatile(
        "cp.async.bulk.shared::cluster.global.mbarrier::complete_tx::bytes "
        "[%0], [%1], %2, [%3];"
        :: "r"(dst), "l"(src), "r"(bytes), "r"(bar) : "memory");
}

// Packed-tile byte offset of the 16B group holding (row, k..k+7).
DINL uint32_t pack_off16(uint32_t row, uint32_t k) {
    uint32_t tile  = (row >> 7) * 16u + (k >> 6);
    uint32_t local = (row & 127u) * 128u + ((k >> 3) & 7u) * 16u;
    local ^= (local >> 3) & 0x70u;           // SW128 swizzle
    return tile * 16384u + local;
}

// Split 8 fp32 values -> packed fp16 hi / scaled-lo words.
DINL void split8(const float* f, uint32_t* hw, uint32_t* lw) {
    #pragma unroll
    for (int j = 0; j < 4; j++) {
        __half h0 = __float2half_rn(f[2 * j + 0]);
        __half h1 = __float2half_rn(f[2 * j + 1]);
        __half l0 = __float2half_rn((f[2 * j + 0] - __half2float(h0)) * LO_SCALE);
        __half l1 = __float2half_rn((f[2 * j + 1] - __half2float(h1)) * LO_SCALE);
        unsigned short uh0 = *reinterpret_cast<unsigned short*>(&h0);
        unsigned short uh1 = *reinterpret_cast<unsigned short*>(&h1);
        unsigned short ul0 = *reinterpret_cast<unsigned short*>(&l0);
        unsigned short ul1 = *reinterpret_cast<unsigned short*>(&l1);
        hw[j] = (uint32_t)uh0 | ((uint32_t)uh1 << 16);
        lw[j] = (uint32_t)ul0 | ((uint32_t)ul1 << 16);
    }
}

// ---------------------------------------------------------------------------
// Block reduction helper (256 threads)
// ---------------------------------------------------------------------------
DINL float block_reduce_sum(float v) {
    __shared__ float sh[8];
    int lane = threadIdx.x & 31;
    int w = threadIdx.x >> 5;
    #pragma unroll
    for (int o = 16; o > 0; o >>= 1) v += __shfl_down_sync(0xFFFFFFFFu, v, o);
    if (lane == 0) sh[w] = v;
    __syncthreads();
    if (w == 0) {
        v = (lane < 8) ? sh[lane] : 0.0f;
        #pragma unroll
        for (int o = 4; o > 0; o >>= 1) v += __shfl_down_sync(0xFFFFFFFFu, v, o);
    }
    return v;
}

// ---------------------------------------------------------------------------
// prep_all: fused full prologue (one launch):
//   blocks [0,16384):       x -> packed (xhi, xlo)
//   blocks [16384,16896):   W_hid -> packed (ahi, alo)
//   blocks [16896,17920):   W_projT -> packed (bthi, btlo), transpose fused
//   blocks [17920,18944):   b_comb[g] = W_hid[g,:]@b_proj + b_hid[g]
// ---------------------------------------------------------------------------
__global__ __launch_bounds__(256)
void prep_all_kernel(const float* __restrict__ x,
                     const float* __restrict__ W_proj,
                     const float* __restrict__ W_hid,
                     const float* __restrict__ b_proj,
                     const float* __restrict__ b_hid,
                     __half* __restrict__ xhi, __half* __restrict__ xlo,
                     __half* __restrict__ ahi, __half* __restrict__ alo,
                     __half* __restrict__ bthi, __half* __restrict__ btlo,
                     float* __restrict__ bcomb)
{
    const int tid = threadIdx.x;
    if (blockIdx.x < 16384) {
        uint32_t i = blockIdx.x * 256 + tid;
        uint32_t row = i >> 7;
        uint32_t k = (i & 127u) * 8u;
        const float4* s = reinterpret_cast<const float4*>(x + ((size_t)row << 10) + k);
        float4 a = s[0], b = s[1];
        float f[8] = {a.x, a.y, a.z, a.w, b.x, b.y, b.z, b.w};
        uint32_t hw[4], lw[4];
        split8(f, hw, lw);
        uint32_t off = pack_off16(row, k);
        *reinterpret_cast<uint4*>(reinterpret_cast<char*>(xhi) + off) =
            make_uint4(hw[0], hw[1], hw[2], hw[3]);
        *reinterpret_cast<uint4*>(reinterpret_cast<char*>(xlo) + off) =
            make_uint4(lw[0], lw[1], lw[2], lw[3]);
    } else if (blockIdx.x < 16896) {
        uint32_t i = (blockIdx.x - 16384) * 256 + tid;
        uint32_t row = i >> 7;
        uint32_t k = (i & 127u) * 8u;
        const float4* s = reinterpret_cast<const float4*>(W_hid + ((size_t)row << 10) + k);
        float4 a = s[0], b = s[1];
        float f[8] = {a.x, a.y, a.z, a.w, b.x, b.y, b.z, b.w};
        uint32_t hw[4], lw[4];
        split8(f, hw, lw);
        uint32_t off = pack_off16(row, k);
        *reinterpret_cast<uint4*>(reinterpret_cast<char*>(ahi) + off) =
            make_uint4(hw[0], hw[1], hw[2], hw[3]);
        *reinterpret_cast<uint4*>(reinterpret_cast<char*>(alo) + off) =
            make_uint4(lw[0], lw[1], lw[2], lw[3]);
    } else if (blockIdx.x < 17920) {
        __shared__ float tile[32][33];
        int t = blockIdx.x - 16896;
        int bx = t & 31;           // d-tile
        int by = t >> 5;           // h-tile
        int tx = tid & 31, ty = tid >> 5;   // ty 0..7
        #pragma unroll
        for (int j = 0; j < 32; j += 8)
            tile[ty + j][tx] = W_proj[(size_t)(by * 32 + ty + j) * 1024 + bx * 32 + tx];
        __syncthreads();
        if (tid < 128) {
            int d_local = tid & 31;
            int grp = tid >> 5;              // 0..3 -> h-group of 8
            float f[8];
            #pragma unroll
            for (int e = 0; e < 8; e++) f[e] = tile[grp * 8 + e][d_local];
            uint32_t hw[4], lw[4];
            split8(f, hw, lw);
            uint32_t row = (uint32_t)(bx * 32 + d_local);
            uint32_t k = (uint32_t)(by * 32 + grp * 8);
            uint32_t off = pack_off16(row, k);
            *reinterpret_cast<uint4*>(reinterpret_cast<char*>(bthi) + off) =
                make_uint4(hw[0], hw[1], hw[2], hw[3]);
            *reinterpret_cast<uint4*>(reinterpret_cast<char*>(btlo) + off) =
                make_uint4(lw[0], lw[1], lw[2], lw[3]);
        }
    } else {
        int g = blockIdx.x - 17920;
        float s = 0.0f;
        for (int h = tid; h < 1024; h += 256)
            s = fmaf(W_hid[g * 1024 + h], b_proj[h], s);
        s = block_reduce_sum(s);
        if (tid == 0) bcomb[g] = s + b_hid[g];
    }
}

// ---------------------------------------------------------------------------
// Shared GEMM constants (main persistent GEMM, 128x128 tiles)
// ---------------------------------------------------------------------------
static constexpr uint32_t AHI_OFF = 0u;
static constexpr uint32_t ALO_OFF = 16384u;
static constexpr uint32_t BHI_OFF = 32768u;
static constexpr uint32_t BLO_OFF = 49152u;
static constexpr uint32_t STAGE   = 65536u;
static constexpr uint32_t SMEM_SZ = 1024u + 3u * STAGE;
static constexpr int NCH = 16;                 // K=1024 / 64

// ---------------------------------------------------------------------------
// Small split-precision GEMM for W_comb: 128(M) x 64(N) tiles, grid (16, 8)
// = 128 CTAs. Warp grid 4x2, warp tile 32x32. Empty-barrier ring mainloop
// (no per-chunk __syncthreads). Bit-identical wcomb output.
// ---------------------------------------------------------------------------
static constexpr uint32_t S_AHI = 0u;
static constexpr uint32_t S_ALO = 16384u;
static constexpr uint32_t S_BHI = 32768u;       // 8 KB (64 rows)
static constexpr uint32_t S_BLO = 40960u;
static constexpr uint32_t S_STAGE = 49152u;     // 48 KB
static constexpr uint32_t S_SMEM = 1024u + 3u * S_STAGE;

__global__ __launch_bounds__(256, 1)
void hmma_gemm_small(const __half* __restrict__ Ahi, const __half* __restrict__ Alo,
                     const __half* __restrict__ Bhi, const __half* __restrict__ Blo,
                     __half* __restrict__ hi_out, __half* __restrict__ lo_out)
{
    extern __shared__ __align__(1024) char smem[];
    const uint32_t sbase = smem_u32(smem);
    const int tid = threadIdx.x;
    const int wid = tid >> 5;
    const int lane = tid & 31;
    const int wm = (wid >> 1) * 32;      // 4 warp rows x 32
    const int wn = (wid & 1) * 32;       // 2 warp cols x 32
    const int m0 = (int)blockIdx.y << 7; // BM = 128
    const int n0 = (int)blockIdx.x << 6; // BN = 64

    float acc1[2][4][4], acc2[2][4][4];
    #pragma unroll
    for (int i = 0; i < 2; i++)
        #pragma unroll
        for (int j = 0; j < 4; j++)
            #pragma unroll
            for (int r = 0; r < 4; r++) { acc1[i][j][r] = 0.0f; acc2[i][j][r] = 0.0f; }

    // full barriers at +0,8,16 ; empty barriers at +24,32,40 (8 warps)
    if (tid == 0) {
        mbar_init(sbase + 0, 1);
        mbar_init(sbase + 8, 1);
        mbar_init(sbase + 16, 1);
        mbar_init(sbase + 24, 8);
        mbar_init(sbase + 32, 8);
        mbar_init(sbase + 40, 8);
    }
    __syncthreads();

    auto issue = [&](int c) {
        const int s = c % 3;
        const int k = c / 3;
        if (k >= 1) mbar_wait(sbase + 24u + (uint32_t)s * 8u, (uint32_t)((k - 1) & 1));
        const uint32_t st  = sbase + 1024u + (uint32_t)s * S_STAGE;
        const uint32_t bar = sbase + (uint32_t)s * 8u;
        mbar_expect_tx(bar, S_STAGE);
        const size_t atile = ((size_t)(blockIdx.y * 16 + c)) << 14;
        const size_t btile = (((size_t)((n0 >> 7) * 16 + c)) << 14) +
                             (size_t)((n0 & 64) ? 8192 : 0);
        bulk_g2s(st + S_AHI, reinterpret_cast<const char*>(Ahi) + atile, 16384u, bar);
        bulk_g2s(st + S_ALO, reinterpret_cast<const char*>(Alo) + atile, 16384u, bar);
        bulk_g2s(st + S_BHI, reinterpret_cast<const char*>(Bhi) + btile, 8192u, bar);
        bulk_g2s(st + S_BLO, reinterpret_cast<const char*>(Blo) + btile, 8192u, bar);
    };

    if (tid == 0) { issue(0); issue(1); }

    #pragma unroll 1
    for (int c = 0; c < NCH; c++) {
        if (tid == 0 && c + 2 < NCH) issue(c + 2);
        mbar_wait(sbase + (uint32_t)(c % 3) * 8u, (uint32_t)((c / 3) & 1));

        const uint32_t st = sbase + 1024u + (uint32_t)(c % 3) * S_STAGE;
        #pragma unroll
        for (int ks = 0; ks < 4; ks++) {
            uint32_t ah[2][4], al[2][4], bh[4][2], bl[4][2];
            #pragma unroll
            for (int i = 0; i < 2; i++) {
                int row = wm + i * 16 + (lane & 15);
                int ch = 2 * ks + (lane >> 4);
                uint32_t off = (uint32_t)(row * 128) +
                               (uint32_t)(((ch ^ (row & 7)) << 4));
                ldsm_x4(ah[i], st + S_AHI + off);
                ldsm_x4(al[i], st + S_ALO + off);
            }
            #pragma unroll
            for (int jj = 0; jj < 2; jj++) {
                int row = wn + jj * 16 + ((lane >> 4) << 3) + (lane & 7);
                int ch = 2 * ks + ((lane >> 3) & 1);
                uint32_t off = (uint32_t)(row * 128) +
                               (uint32_t)(((ch ^ (row & 7)) << 4));
                uint32_t t[4];
                ldsm_x4(t, st + S_BHI + off);
                bh[2 * jj][0] = t[0]; bh[2 * jj][1] = t[1];
                bh[2 * jj + 1][0] = t[2]; bh[2 * jj + 1][1] = t[3];
                ldsm_x4(t, st + S_BLO + off);
                bl[2 * jj][0] = t[0]; bl[2 * jj][1] = t[1];
                bl[2 * jj + 1][0] = t[2]; bl[2 * jj + 1][1] = t[3];
            }
            #pragma unroll
            for (int i = 0; i < 2; i++)
                #pragma unroll
                for (int j = 0; j < 4; j++) {
                    mma_f16(acc1[i][j], ah[i], bh[j]);
                    mma_f16(acc2[i][j], al[i], bh[j]);
                    mma_f16(acc2[i][j], ah[i], bl[j]);
                }
        }
        if (lane == 0) mbar_arrive(sbase + 24u + (uint32_t)(c % 3) * 8u);
    }
    __syncthreads();

    // Epilogue: combine -> padded smem [128][68] -> packed fp16 split output
    float* stg = reinterpret_cast<float*>(smem + 1024);
    #pragma unroll
    for (int i = 0; i < 2; i++) {
        int row = wm + i * 16 + (lane >> 2);
        #pragma unroll
        for (int j = 0; j < 4; j++) {
            int col = wn + j * 8 + (lane & 3) * 2;
            stg[row * 68 + col]           = fmaf(acc2[i][j][0], LO_INV, acc1[i][j][0]);
            stg[row * 68 + col + 1]       = fmaf(acc2[i][j][1], LO_INV, acc1[i][j][1]);
            stg[(row + 8) * 68 + col]     = fmaf(acc2[i][j][2], LO_INV, acc1[i][j][2]);
            stg[(row + 8) * 68 + col + 1] = fmaf(acc2[i][j][3], LO_INV, acc1[i][j][3]);
        }
    }
    __syncthreads();

    #pragma unroll
    for (int it = 0; it < 4; it++) {
        int g = it * 256 + tid;          // 1024 8-elem groups
        int r = g >> 3;
        int c8 = (g & 7) << 3;
        float4 va = *reinterpret_cast<const float4*>(&stg[r * 68 + c8]);
        float4 vb = *reinterpret_cast<const float4*>(&stg[r * 68 + c8 + 4]);
        float f[8] = {va.x, va.y, va.z, va.w, vb.x, vb.y, vb.z, vb.w};
        uint32_t hw[4], lw[4];
        split8(f, hw, lw);
        uint32_t off = pack_off16((uint32_t)(m0 + r), (uint32_t)(n0 + c8));
        *reinterpret_cast<uint4*>(reinterpret_cast<char*>(hi_out) + off) =
            make_uint4(hw[0], hw[1], hw[2], hw[3]);
        *reinterpret_cast<uint4*>(reinterpret_cast<char*>(lo_out) + off) =
            make_uint4(lw[0], lw[1], lw[2], lw[3]);
    }
}

// ---------------------------------------------------------------------------
// PERSISTENT main GEMM with full/empty mbarrier rings (no __syncthreads in
// the mainloop).
// ---------------------------------------------------------------------------
static constexpr int PGRID = 148;
static constexpr int NTILES = 2048;

__global__ __launch_bounds__(256, 1)
void hmma_gemm_persistent(const __half* __restrict__ Ahi,
                          const __half* __restrict__ Alo,
                          const __half* __restrict__ Bhi,
                          const __half* __restrict__ Blo,
                          const float* __restrict__ bias,
                          float* __restrict__ fout)
{
    extern __shared__ __align__(1024) char smem[];
    const uint32_t sbase = smem_u32(smem);
    const int tid = threadIdx.x;
    const int wid = tid >> 5;
    const int lane = tid & 31;
    const int wm = (wid >> 2) * 64;
    const int wn = (wid & 3) * 32;

    int ntile = 0;
    for (int t = blockIdx.x; t < NTILES; t += PGRID) ntile++;
    const int G = ntile * NCH;

    if (tid == 0) {
        mbar_init(sbase + 0, 1);
        mbar_init(sbase + 8, 1);
        mbar_init(sbase + 16, 1);
        mbar_init(sbase + 24, 8);
        mbar_init(sbase + 32, 8);
        mbar_init(sbase + 40, 8);
    }
    __syncthreads();

    auto issue = [&](int g) {
        const int s = g % 3;
        const int k = g / 3;
        if (k >= 1) mbar_wait(sbase + 24u + (uint32_t)s * 8u, (uint32_t)((k - 1) & 1));
        const uint32_t st  = sbase + 1024u + (uint32_t)s * STAGE;
        const uint32_t bar = sbase + (uint32_t)s * 8u;
        const int tile = blockIdx.x + (g >> 4) * PGRID;
        const int c = g & 15;
        mbar_expect_tx(bar, STAGE);
        const size_t atile = ((size_t)((tile >> 3) * 16 + c)) << 14;
        const size_t btile = ((size_t)((tile & 7) * 16 + c)) << 14;
        bulk_g2s(st + AHI_OFF, reinterpret_cast<const char*>(Ahi) + atile, 16384u, bar);
        bulk_g2s(st + ALO_OFF, reinterpret_cast<const char*>(Alo) + atile, 16384u, bar);
        bulk_g2s(st + BHI_OFF, reinterpret_cast<const char*>(Bhi) + btile, 16384u, bar);
        bulk_g2s(st + BLO_OFF, reinterpret_cast<const char*>(Blo) + btile, 16384u, bar);
    };

    float acc1[4][4][4], acc2[4][4][4];
    #pragma unroll
    for (int i = 0; i < 4; i++)
        #pragma unroll
        for (int j = 0; j < 4; j++)
            #pragma unroll
            for (int r = 0; r < 4; r++) { acc1[i][j][r] = 0.0f; acc2[i][j][r] = 0.0f; }

    if (tid == 0) { issue(0); if (G > 1) issue(1); }

    #pragma unroll 1
    for (int g = 0; g < G; g++) {
        if (tid == 0 && g + 2 < G) issue(g + 2);
        mbar_wait(sbase + (uint32_t)(g % 3) * 8u, (uint32_t)((g / 3) & 1));

        const uint32_t st = sbase + 1024u + (uint32_t)(g % 3) * STAGE;
        #pragma unroll
        for (int ks = 0; ks < 4; ks++) {
            uint32_t ah[4][4], al[4][4], bh[4][2], bl[4][2];
            #pragma unroll
            for (int i = 0; i < 4; i++) {
                int row = wm + i * 16 + (lane & 15);
                int ch = 2 * ks + (lane >> 4);
                uint32_t off = (uint32_t)(row * 128) +
                               (uint32_t)(((ch ^ (row & 7)) << 4));
                ldsm_x4(ah[i], st + AHI_OFF + off);
                ldsm_x4(al[i], st + ALO_OFF + off);
            }
            #pragma unroll
            for (int jj = 0; jj < 2; jj++) {
                int row = wn + jj * 16 + ((lane >> 4) << 3) + (lane & 7);
                int ch = 2 * ks + ((lane >> 3) & 1);
                uint32_t off = (uint32_t)(row * 128) +
                               (uint32_t)(((ch ^ (row & 7)) << 4));
                uint32_t t[4];
                ldsm_x4(t, st + BHI_OFF + off);
                bh[2 * jj][0] = t[0]; bh[2 * jj][1] = t[1];
                bh[2 * jj + 1][0] = t[2]; bh[2 * jj + 1][1] = t[3];
                ldsm_x4(t, st + BLO_OFF + off);
                bl[2 * jj][0] = t[0]; bl[2 * jj][1] = t[1];
                bl[2 * jj + 1][0] = t[2]; bl[2 * jj + 1][1] = t[3];
            }
            #pragma unroll
            for (int i = 0; i < 4; i++)
                #pragma unroll
                for (int j = 0; j < 4; j++) {
                    mma_f16(acc1[i][j], ah[i], bh[j]);
                    mma_f16(acc2[i][j], al[i], bh[j]);
                    mma_f16(acc2[i][j], ah[i], bl[j]);
                }
        }

        if (lane == 0) mbar_arrive(sbase + 24u + (uint32_t)(g % 3) * 8u);

        if ((g & 15) == 15) {
            const int tile = blockIdx.x + (g >> 4) * PGRID;
            const int m0 = (tile >> 3) << 7;
            const int n0 = (tile & 7) << 7;
            #pragma unroll
            for (int i = 0; i < 4; i++) {
                int row = m0 + wm + i * 16 + (lane >> 2);
                #pragma unroll
                for (int j = 0; j < 4; j++) {
                    int col = n0 + wn + j * 8 + (lane & 3) * 2;
                    float b0 = __ldg(bias + col);
                    float b1 = __ldg(bias + col + 1);
                    float2 v0, v1;
                    v0.x = fmaf(acc2[i][j][0], LO_INV, acc1[i][j][0]) + b0;
                    v0.y = fmaf(acc2[i][j][1], LO_INV, acc1[i][j][1]) + b1;
                    v1.x = fmaf(acc2[i][j][2], LO_INV, acc1[i][j][2]) + b0;
                    v1.y = fmaf(acc2[i][j][3], LO_INV, acc1[i][j][3]) + b1;
                    *reinterpret_cast<float2*>(&fout[(size_t)row * 1024 + col]) = v0;
                    *reinterpret_cast<float2*>(&fout[(size_t)(row + 8) * 1024 + col]) = v1;
                    acc1[i][j][0] = 0.0f; acc1[i][j][1] = 0.0f;
                    acc1[i][j][2] = 0.0f; acc1[i][j][3] = 0.0f;
                    acc2[i][j][0] = 0.0f; acc2[i][j][1] = 0.0f;
                    acc2[i][j][2] = 0.0f; acc2[i][j][3] = 0.0f;
                }
            }
        }
    }
}

// ---------------------------------------------------------------------------
// SEGMENTED LIF scan: 8 segments of 128 steps, 32-step decay warm-up.
// cp.async DOUBLE-buffered smem staging (32 KB -> 7 CTAs/SM). Batch k+2
// reuses buffer k%2 strictly after batch k is consumed. Same arithmetic.
// ---------------------------------------------------------------------------
__global__ __launch_bounds__(64)
void lif_kernel(const float* __restrict__ h2, float* __restrict__ pooled8)
{
    __shared__ __align__(16) float4 buf[2][16][64];   // 32 KB
    const int tid = threadIdx.x;
    int idx = blockIdx.x * 64 + tid;            // 0..65535
    int seg = idx >> 13;                        // 0..7
    int col = idx & 8191;
    int b = col >> 8;
    int g4 = col & 255;
    const float4* p = reinterpret_cast<const float4*>(h2 + ((size_t)b << 20)) + g4;

    const int t_start = seg << 7;
    const int warm = (seg > 0) ? 32 : 0;
    const int t_first = t_start - warm;
    const int nbatch = (128 + warm) >> 4;       // 8 or 10

    const uint32_t sbuf = smem_u32(&buf[0][0][tid]);
    auto issue_batch = [&](int k) {
        const float4* src = p + (size_t)(t_first + k * 16) * 256;
        uint32_t dst = sbuf + (uint32_t)(k & 1) * 16384u;
        #pragma unroll
        for (int i = 0; i < 16; i++)
            cp16(dst + (uint32_t)i * 1024u, src + (size_t)i * 256);
        cp_commit();
    };

    issue_batch(0);
    issue_batch(1);

    float v[4] = {0, 0, 0, 0}, acc[4] = {0, 0, 0, 0};
    const int warm_batches = warm >> 4;          // 0 or 2

    #pragma unroll 1
    for (int k = 0; k < nbatch; k++) {
        if (k + 1 < nbatch) cp_wait<1>(); else cp_wait<0>();
        const float4* bk = &buf[k & 1][0][tid];
        if (k < warm_batches) {
            #pragma unroll
            for (int i = 0; i < 16; i++) {
                float4 xv = bk[i * 64];
                float xs[4] = {xv.x, xv.y, xv.z, xv.w};
                #pragma unroll
                for (int c = 0; c < 4; c++) {
                    v[c] = __fadd_rn(v[c], __fmul_rn(__fsub_rn(xs[c], v[c]), 0.5f));
                    if (v[c] >= 1.0f) v[c] = __fsub_rn(v[c], 1.0f);
                }
            }
        } else {
            #pragma unroll
            for (int i = 0; i < 16; i++) {
                float4 xv = bk[i * 64];
                float xs[4] = {xv.x, xv.y, xv.z, xv.w};
                #pragma unroll
                for (int c = 0; c < 4; c++) {
                    v[c] = __fadd_rn(v[c], __fmul_rn(__fsub_rn(xs[c], v[c]), 0.5f));
                    if (v[c] >= 1.0f) { acc[c] += 1.0f; v[c] = __fsub_rn(v[c], 1.0f); }
                }
            }
        }
        if (k + 2 < nbatch) issue_batch(k + 2);
    }

    float4 r;
    r.x = acc[0] * (1.0f / 1024.0f); r.y = acc[1] * (1.0f / 1024.0f);
    r.z = acc[2] * (1.0f / 1024.0f); r.w = acc[3] * (1.0f / 1024.0f);
    reinterpret_cast<float4*>(pooled8)[idx] = r;   // [seg][b][g4] layout
}

// ---------------------------------------------------------------------------
// out[b,o] = sum_g (sum_seg pooled8[seg,b,g]) * W_out[o,g] + b_out[o]
// ---------------------------------------------------------------------------
__global__ __launch_bounds__(256)
void head_kernel(const float* __restrict__ pooled8,
                 const float* __restrict__ W_out,
                 const float* __restrict__ b_out,
                 float* __restrict__ out)
{
    int b = blockIdx.x / 10;
    int o = blockIdx.x % 10;
    float s = 0.0f;
    for (int g = threadIdx.x; g < 1024; g += 256) {
        float pv = 0.0f;
        #pragma unroll
        for (int sg = 0; sg < 8; sg++)
            pv += pooled8[sg * 32768 + b * 1024 + g];
        s = fmaf(pv, W_out[o * 1024 + g], s);
    }
    s = block_reduce_sum(s);
    if (threadIdx.x == 0) out[blockIdx.x] = s + b_out[o];
}

// ---------------------------------------------------------------------------
extern "C" void kernel_launch(void* const* d_in, const int* in_sizes, int n_in,
                              void* d_out, int out_size)
{
    (void)in_sizes; (void)n_in; (void)out_size;
    const float* x      = (const float*)d_in[0];
    const float* W_proj = (const float*)d_in[1];
    const float* b_proj = (const float*)d_in[2];
    const float* W_hid  = (const float*)d_in[3];
    const float* b_hid  = (const float*)d_in[4];
    const float* W_out  = (const float*)d_in[5];
    const float* b_out  = (const float*)d_in[6];
    float* out = (float*)d_out;

    float *bcomb, *h2, *pooled8;
    __half *xhi, *xlo, *whi, *wlo, *ahi, *alo, *bthi, *btlo;
    cudaGetSymbolAddress((void**)&bcomb,   g_bcomb);
    cudaGetSymbolAddress((void**)&h2,      g_h2);
    cudaGetSymbolAddress((void**)&pooled8, g_pooled8);
    cudaGetSymbolAddress((void**)&xhi,     g_xhi);
    cudaGetSymbolAddress((void**)&xlo,     g_xlo);
    cudaGetSymbolAddress((void**)&whi,     g_whi);
    cudaGetSymbolAddress((void**)&wlo,     g_wlo);
    cudaGetSymbolAddress((void**)&ahi,     g_ahi);
    cudaGetSymbolAddress((void**)&alo,     g_alo);
    cudaGetSymbolAddress((void**)&bthi,    g_bthi);
    cudaGetSymbolAddress((void**)&btlo,    g_btlo);

    cudaFuncSetAttribute(hmma_gemm_small,
                         cudaFuncAttributeMaxDynamicSharedMemorySize, (int)S_SMEM);
    cudaFuncSetAttribute(hmma_gemm_persistent,
                         cudaFuncAttributeMaxDynamicSharedMemorySize, (int)SMEM_SZ);

    // 1) fused prologue: x split + W_hid split + W_projT split + b_comb
    prep_all_kernel<<<18944, 256>>>(x, W_proj, W_hid, b_proj, b_hid,
                                    xhi, xlo, ahi, alo, bthi, btlo, bcomb);
    // 2) W_comb = W_hid @ W_projT^T, packed split output (128 CTAs)
    hmma_gemm_small<<<dim3(16, 8), 256, S_SMEM>>>(
        ahi, alo, bthi, btlo, whi, wlo);
    // 3) h2 = x @ W_comb^T + b_comb   (persistent, sync-free mainloop)
    hmma_gemm_persistent<<<PGRID, 256, SMEM_SZ>>>(
        xhi, xlo, whi, wlo, bcomb, h2);
    // 4) segmented LIF (8 segments, cp.async double-buffered) + partial pool
    lif_kernel<<<1024, 64>>>(h2, pooled8);
    // 5) head over summed segments
    head_kernel<<<320, 256>>>(pooled8, W_out, b_out, out);
}

// round 16
// speedup vs baseline: 1.0050x; 1.0050x over previous
#include <cuda_runtime.h>
#include <cuda_fp16.h>
#include <cstdint>
#include <cstddef>

#define DINL __device__ __forceinline__

// ---------------------------------------------------------------------------
// Scratch (device globals; no allocation allowed)
// Packed layout for all fp16 GEMM operands: 16 KB tiles of (128 rows x 64 k),
// row-major over (rowtile, ktile), interior pre-swizzled for ldmatrix.
// ---------------------------------------------------------------------------
__device__ float g_bcomb[1024];
__device__ float g_h2[32u * 1024u * 1024u];     // [B*T, H] fp32 (134 MB)
__device__ float g_pooled8[8 * 32 * 1024];      // per-segment partial pools
__device__ __align__(128) __half g_xhi[32u * 1024u * 1024u];
__device__ __align__(128) __half g_xlo[32u * 1024u * 1024u];
__device__ __align__(128) __half g_whi[1024u * 1024u];
__device__ __align__(128) __half g_wlo[1024u * 1024u];
__device__ __align__(128) __half g_ahi[1024u * 1024u];   // W_hid split
__device__ __align__(128) __half g_alo[1024u * 1024u];
__device__ __align__(128) __half g_bthi[1024u * 1024u];  // W_projT split
__device__ __align__(128) __half g_btlo[1024u * 1024u];

// Residual scale: lo' = (x - hi) * 2^12, combined as acc1 + acc2 * 2^-12.
static constexpr float LO_SCALE = 4096.0f;
static constexpr float LO_INV   = 1.0f / 4096.0f;

// ---------------------------------------------------------------------------
// PTX helpers (compute_103 baseline-safe)
// ---------------------------------------------------------------------------
DINL uint32_t smem_u32(const void* p) {
    uint32_t r;
    asm("{ .reg .u64 t; cvta.to.shared.u64 t, %1; cvt.u32.u64 %0, t; }"
        : "=r"(r) : "l"(p));
    return r;
}
DINL void cp16(uint32_t dst, const void* src) {
    asm volatile("cp.async.cg.shared.global [%0], [%1], 16;"
                 :: "r"(dst), "l"(src) : "memory");
}
DINL void cp_commit() { asm volatile("cp.async.commit_group;" ::: "memory"); }
template <int N> DINL void cp_wait() {
    asm volatile("cp.async.wait_group %0;" :: "n"(N) : "memory");
}
DINL void ldsm_x4(uint32_t* r, uint32_t addr) {
    asm volatile("ldmatrix.sync.aligned.m8n8.x4.shared.b16 {%0,%1,%2,%3}, [%4];"
                 : "=r"(r[0]), "=r"(r[1]), "=r"(r[2]), "=r"(r[3]) : "r"(addr));
}
DINL void mma_f16(float* d, const uint32_t* a, const uint32_t* b) {
    asm volatile(
        "mma.sync.aligned.m16n8k16.row.col.f32.f16.f16.f32 "
        "{%0,%1,%2,%3}, {%4,%5,%6,%7}, {%8,%9}, {%0,%1,%2,%3};"
        : "+f"(d[0]), "+f"(d[1]), "+f"(d[2]), "+f"(d[3])
        : "r"(a[0]), "r"(a[1]), "r"(a[2]), "r"(a[3]), "r"(b[0]), "r"(b[1]));
}
DINL void mbar_init(uint32_t addr, uint32_t cnt) {
    asm volatile("mbarrier.init.shared.b64 [%0], %1;" :: "r"(addr), "r"(cnt) : "memory");
}
DINL void mbar_expect_tx(uint32_t addr, uint32_t bytes) {
    asm volatile("mbarrier.arrive.expect_tx.shared.b64 _, [%0], %1;"
                 :: "r"(addr), "r"(bytes) : "memory");
}
DINL void mbar_arrive(uint32_t addr) {
    asm volatile("mbarrier.arrive.shared.b64 _, [%0];" :: "r"(addr) : "memory");
}
DINL void mbar_wait(uint32_t addr, uint32_t parity) {
    asm volatile(
        "{\n\t.reg .pred P;\n"
        "W1_%=:\n\tmbarrier.try_wait.parity.acquire.cta.shared::cta.b64 P, [%0], %1, 0x989680;\n\t"
        "@P bra W2_%=;\n\tbra W1_%=;\nW2_%=:\n\t}"
        :: "r"(addr), "r"(parity) : "memory");
}
// 1D bulk async copy global->smem, completion via mbarrier complete_tx.
DINL void bulk_g2s(uint32_t dst, const void* src, uint32_t bytes, uint32_t bar) {
    asm volatile(
        "cp.async.bulk.shared::cluster.global.mbarrier::complete_tx::bytes "
        "[%0], [%1], %2, [%3];"
        :: "r"(dst), "l"(src), "r"(bytes), "r"(bar) : "memory");
}

// Packed-tile byte offset of the 16B group holding (row, k..k+7).
DINL uint32_t pack_off16(uint32_t row, uint32_t k) {
    uint32_t tile  = (row >> 7) * 16u + (k >> 6);
    uint32_t local = (row & 127u) * 128u + ((k >> 3) & 7u) * 16u;
    local ^= (local >> 3) & 0x70u;           // SW128 swizzle
    return tile * 16384u + local;
}

// Split 8 fp32 values -> packed fp16 hi / scaled-lo words.
DINL void split8(const float* f, uint32_t* hw, uint32_t* lw) {
    #pragma unroll
    for (int j = 0; j < 4; j++) {
        __half h0 = __float2half_rn(f[2 * j + 0]);
        __half h1 = __float2half_rn(f[2 * j + 1]);
        __half l0 = __float2half_rn((f[2 * j + 0] - __half2float(h0)) * LO_SCALE);
        __half l1 = __float2half_rn((f[2 * j + 1] - __half2float(h1)) * LO_SCALE);
        unsigned short uh0 = *reinterpret_cast<unsigned short*>(&h0);
        unsigned short uh1 = *reinterpret_cast<unsigned short*>(&h1);
        unsigned short ul0 = *reinterpret_cast<unsigned short*>(&l0);
        unsigned short ul1 = *reinterpret_cast<unsigned short*>(&l1);
        hw[j] = (uint32_t)uh0 | ((uint32_t)uh1 << 16);
        lw[j] = (uint32_t)ul0 | ((uint32_t)ul1 << 16);
    }
}

// ---------------------------------------------------------------------------
// Block reduction helper (256 threads)
// ---------------------------------------------------------------------------
DINL float block_reduce_sum(float v) {
    __shared__ float sh[8];
    int lane = threadIdx.x & 31;
    int w = threadIdx.x >> 5;
    #pragma unroll
    for (int o = 16; o > 0; o >>= 1) v += __shfl_down_sync(0xFFFFFFFFu, v, o);
    if (lane == 0) sh[w] = v;
    __syncthreads();
    if (w == 0) {
        v = (lane < 8) ? sh[lane] : 0.0f;
        #pragma unroll
        for (int o = 4; o > 0; o >>= 1) v += __shfl_down_sync(0xFFFFFFFFu, v, o);
    }
    return v;
}

// ---------------------------------------------------------------------------
// prep_all: fused full prologue (one launch):
//   blocks [0,16384):       x -> packed (xhi, xlo)
//   blocks [16384,16896):   W_hid -> packed (ahi, alo)
//   blocks [16896,17920):   W_projT -> packed (bthi, btlo), transpose fused
//   blocks [17920,18944):   b_comb[g] = W_hid[g,:]@b_proj + b_hid[g]
// ---------------------------------------------------------------------------
__global__ __launch_bounds__(256)
void prep_all_kernel(const float* __restrict__ x,
                     const float* __restrict__ W_proj,
                     const float* __restrict__ W_hid,
                     const float* __restrict__ b_proj,
                     const float* __restrict__ b_hid,
                     __half* __restrict__ xhi, __half* __restrict__ xlo,
                     __half* __restrict__ ahi, __half* __restrict__ alo,
                     __half* __restrict__ bthi, __half* __restrict__ btlo,
                     float* __restrict__ bcomb)
{
    const int tid = threadIdx.x;
    if (blockIdx.x < 16384) {
        uint32_t i = blockIdx.x * 256 + tid;
        uint32_t row = i >> 7;
        uint32_t k = (i & 127u) * 8u;
        const float4* s = reinterpret_cast<const float4*>(x + ((size_t)row << 10) + k);
        float4 a = s[0], b = s[1];
        float f[8] = {a.x, a.y, a.z, a.w, b.x, b.y, b.z, b.w};
        uint32_t hw[4], lw[4];
        split8(f, hw, lw);
        uint32_t off = pack_off16(row, k);
        *reinterpret_cast<uint4*>(reinterpret_cast<char*>(xhi) + off) =
            make_uint4(hw[0], hw[1], hw[2], hw[3]);
        *reinterpret_cast<uint4*>(reinterpret_cast<char*>(xlo) + off) =
            make_uint4(lw[0], lw[1], lw[2], lw[3]);
    } else if (blockIdx.x < 16896) {
        uint32_t i = (blockIdx.x - 16384) * 256 + tid;
        uint32_t row = i >> 7;
        uint32_t k = (i & 127u) * 8u;
        const float4* s = reinterpret_cast<const float4*>(W_hid + ((size_t)row << 10) + k);
        float4 a = s[0], b = s[1];
        float f[8] = {a.x, a.y, a.z, a.w, b.x, b.y, b.z, b.w};
        uint32_t hw[4], lw[4];
        split8(f, hw, lw);
        uint32_t off = pack_off16(row, k);
        *reinterpret_cast<uint4*>(reinterpret_cast<char*>(ahi) + off) =
            make_uint4(hw[0], hw[1], hw[2], hw[3]);
        *reinterpret_cast<uint4*>(reinterpret_cast<char*>(alo) + off) =
            make_uint4(lw[0], lw[1], lw[2], lw[3]);
    } else if (blockIdx.x < 17920) {
        __shared__ float tile[32][33];
        int t = blockIdx.x - 16896;
        int bx = t & 31;           // d-tile
        int by = t >> 5;           // h-tile
        int tx = tid & 31, ty = tid >> 5;   // ty 0..7
        #pragma unroll
        for (int j = 0; j < 32; j += 8)
            tile[ty + j][tx] = W_proj[(size_t)(by * 32 + ty + j) * 1024 + bx * 32 + tx];
        __syncthreads();
        if (tid < 128) {
            int d_local = tid & 31;
            int grp = tid >> 5;              // 0..3 -> h-group of 8
            float f[8];
            #pragma unroll
            for (int e = 0; e < 8; e++) f[e] = tile[grp * 8 + e][d_local];
            uint32_t hw[4], lw[4];
            split8(f, hw, lw);
            uint32_t row = (uint32_t)(bx * 32 + d_local);
            uint32_t k = (uint32_t)(by * 32 + grp * 8);
            uint32_t off = pack_off16(row, k);
            *reinterpret_cast<uint4*>(reinterpret_cast<char*>(bthi) + off) =
                make_uint4(hw[0], hw[1], hw[2], hw[3]);
            *reinterpret_cast<uint4*>(reinterpret_cast<char*>(btlo) + off) =
                make_uint4(lw[0], lw[1], lw[2], lw[3]);
        }
    } else {
        int g = blockIdx.x - 17920;
        float s = 0.0f;
        for (int h = tid; h < 1024; h += 256)
            s = fmaf(W_hid[g * 1024 + h], b_proj[h], s);
        s = block_reduce_sum(s);
        if (tid == 0) bcomb[g] = s + b_hid[g];
    }
}

// ---------------------------------------------------------------------------
// Shared GEMM constants (main persistent GEMM, 128x128 tiles)
// ---------------------------------------------------------------------------
static constexpr uint32_t AHI_OFF = 0u;
static constexpr uint32_t ALO_OFF = 16384u;
static constexpr uint32_t BHI_OFF = 32768u;
static constexpr uint32_t BLO_OFF = 49152u;
static constexpr uint32_t STAGE   = 65536u;
static constexpr uint32_t SMEM_SZ = 1024u + 3u * STAGE;
static constexpr int NCH = 16;                 // K=1024 / 64

// ---------------------------------------------------------------------------
// Small split-precision GEMM for W_comb: 128(M) x 64(N) tiles, grid (16, 8)
// = 128 CTAs. Warp grid 4x2, warp tile 32x32. Empty-barrier ring mainloop.
// Bit-identical wcomb output.
// ---------------------------------------------------------------------------
static constexpr uint32_t S_AHI = 0u;
static constexpr uint32_t S_ALO = 16384u;
static constexpr uint32_t S_BHI = 32768u;       // 8 KB (64 rows)
static constexpr uint32_t S_BLO = 40960u;
static constexpr uint32_t S_STAGE = 49152u;     // 48 KB
static constexpr uint32_t S_SMEM = 1024u + 3u * S_STAGE;

__global__ __launch_bounds__(256, 1)
void hmma_gemm_small(const __half* __restrict__ Ahi, const __half* __restrict__ Alo,
                     const __half* __restrict__ Bhi, const __half* __restrict__ Blo,
                     __half* __restrict__ hi_out, __half* __restrict__ lo_out)
{
    extern __shared__ __align__(1024) char smem[];
    const uint32_t sbase = smem_u32(smem);
    const int tid = threadIdx.x;
    const int wid = tid >> 5;
    const int lane = tid & 31;
    const int wm = (wid >> 1) * 32;      // 4 warp rows x 32
    const int wn = (wid & 1) * 32;       // 2 warp cols x 32
    const int m0 = (int)blockIdx.y << 7; // BM = 128
    const int n0 = (int)blockIdx.x << 6; // BN = 64

    float acc1[2][4][4], acc2[2][4][4];
    #pragma unroll
    for (int i = 0; i < 2; i++)
        #pragma unroll
        for (int j = 0; j < 4; j++)
            #pragma unroll
            for (int r = 0; r < 4; r++) { acc1[i][j][r] = 0.0f; acc2[i][j][r] = 0.0f; }

    if (tid == 0) {
        mbar_init(sbase + 0, 1);
        mbar_init(sbase + 8, 1);
        mbar_init(sbase + 16, 1);
        mbar_init(sbase + 24, 8);
        mbar_init(sbase + 32, 8);
        mbar_init(sbase + 40, 8);
    }
    __syncthreads();

    auto issue = [&](int c) {
        const int s = c % 3;
        const int k = c / 3;
        if (k >= 1) mbar_wait(sbase + 24u + (uint32_t)s * 8u, (uint32_t)((k - 1) & 1));
        const uint32_t st  = sbase + 1024u + (uint32_t)s * S_STAGE;
        const uint32_t bar = sbase + (uint32_t)s * 8u;
        mbar_expect_tx(bar, S_STAGE);
        const size_t atile = ((size_t)(blockIdx.y * 16 + c)) << 14;
        const size_t btile = (((size_t)((n0 >> 7) * 16 + c)) << 14) +
                             (size_t)((n0 & 64) ? 8192 : 0);
        bulk_g2s(st + S_AHI, reinterpret_cast<const char*>(Ahi) + atile, 16384u, bar);
        bulk_g2s(st + S_ALO, reinterpret_cast<const char*>(Alo) + atile, 16384u, bar);
        bulk_g2s(st + S_BHI, reinterpret_cast<const char*>(Bhi) + btile, 8192u, bar);
        bulk_g2s(st + S_BLO, reinterpret_cast<const char*>(Blo) + btile, 8192u, bar);
    };

    if (tid == 0) { issue(0); issue(1); }

    #pragma unroll 1
    for (int c = 0; c < NCH; c++) {
        if (tid == 0 && c + 2 < NCH) issue(c + 2);
        mbar_wait(sbase + (uint32_t)(c % 3) * 8u, (uint32_t)((c / 3) & 1));

        const uint32_t st = sbase + 1024u + (uint32_t)(c % 3) * S_STAGE;
        #pragma unroll
        for (int ks = 0; ks < 4; ks++) {
            uint32_t ah[2][4], al[2][4], bh[4][2], bl[4][2];
            #pragma unroll
            for (int i = 0; i < 2; i++) {
                int row = wm + i * 16 + (lane & 15);
                int ch = 2 * ks + (lane >> 4);
                uint32_t off = (uint32_t)(row * 128) +
                               (uint32_t)(((ch ^ (row & 7)) << 4));
                ldsm_x4(ah[i], st + S_AHI + off);
                ldsm_x4(al[i], st + S_ALO + off);
            }
            #pragma unroll
            for (int jj = 0; jj < 2; jj++) {
                int row = wn + jj * 16 + ((lane >> 4) << 3) + (lane & 7);
                int ch = 2 * ks + ((lane >> 3) & 1);
                uint32_t off = (uint32_t)(row * 128) +
                               (uint32_t)(((ch ^ (row & 7)) << 4));
                uint32_t t[4];
                ldsm_x4(t, st + S_BHI + off);
                bh[2 * jj][0] = t[0]; bh[2 * jj][1] = t[1];
                bh[2 * jj + 1][0] = t[2]; bh[2 * jj + 1][1] = t[3];
                ldsm_x4(t, st + S_BLO + off);
                bl[2 * jj][0] = t[0]; bl[2 * jj][1] = t[1];
                bl[2 * jj + 1][0] = t[2]; bl[2 * jj + 1][1] = t[3];
            }
            #pragma unroll
            for (int i = 0; i < 2; i++)
                #pragma unroll
                for (int j = 0; j < 4; j++) {
                    mma_f16(acc1[i][j], ah[i], bh[j]);
                    mma_f16(acc2[i][j], al[i], bh[j]);
                    mma_f16(acc2[i][j], ah[i], bl[j]);
                }
        }
        if (lane == 0) mbar_arrive(sbase + 24u + (uint32_t)(c % 3) * 8u);
    }
    __syncthreads();

    // Epilogue: combine -> padded smem [128][68] -> packed fp16 split output
    float* stg = reinterpret_cast<float*>(smem + 1024);
    #pragma unroll
    for (int i = 0; i < 2; i++) {
        int row = wm + i * 16 + (lane >> 2);
        #pragma unroll
        for (int j = 0; j < 4; j++) {
            int col = wn + j * 8 + (lane & 3) * 2;
            stg[row * 68 + col]           = fmaf(acc2[i][j][0], LO_INV, acc1[i][j][0]);
            stg[row * 68 + col + 1]       = fmaf(acc2[i][j][1], LO_INV, acc1[i][j][1]);
            stg[(row + 8) * 68 + col]     = fmaf(acc2[i][j][2], LO_INV, acc1[i][j][2]);
            stg[(row + 8) * 68 + col + 1] = fmaf(acc2[i][j][3], LO_INV, acc1[i][j][3]);
        }
    }
    __syncthreads();

    #pragma unroll
    for (int it = 0; it < 4; it++) {
        int g = it * 256 + tid;          // 1024 8-elem groups
        int r = g >> 3;
        int c8 = (g & 7) << 3;
        float4 va = *reinterpret_cast<const float4*>(&stg[r * 68 + c8]);
        float4 vb = *reinterpret_cast<const float4*>(&stg[r * 68 + c8 + 4]);
        float f[8] = {va.x, va.y, va.z, va.w, vb.x, vb.y, vb.z, vb.w};
        uint32_t hw[4], lw[4];
        split8(f, hw, lw);
        uint32_t off = pack_off16((uint32_t)(m0 + r), (uint32_t)(n0 + c8));
        *reinterpret_cast<uint4*>(reinterpret_cast<char*>(hi_out) + off) =
            make_uint4(hw[0], hw[1], hw[2], hw[3]);
        *reinterpret_cast<uint4*>(reinterpret_cast<char*>(lo_out) + off) =
            make_uint4(lw[0], lw[1], lw[2], lw[3]);
    }
}

// ---------------------------------------------------------------------------
// PERSISTENT main GEMM with full/empty mbarrier rings (no __syncthreads in
// the mainloop).
// ---------------------------------------------------------------------------
static constexpr int PGRID = 148;
static constexpr int NTILES = 2048;

__global__ __launch_bounds__(256, 1)
void hmma_gemm_persistent(const __half* __restrict__ Ahi,
                          const __half* __restrict__ Alo,
                          const __half* __restrict__ Bhi,
                          const __half* __restrict__ Blo,
                          const float* __restrict__ bias,
                          float* __restrict__ fout)
{
    extern __shared__ __align__(1024) char smem[];
    const uint32_t sbase = smem_u32(smem);
    const int tid = threadIdx.x;
    const int wid = tid >> 5;
    const int lane = tid & 31;
    const int wm = (wid >> 2) * 64;
    const int wn = (wid & 3) * 32;

    int ntile = 0;
    for (int t = blockIdx.x; t < NTILES; t += PGRID) ntile++;
    const int G = ntile * NCH;

    if (tid == 0) {
        mbar_init(sbase + 0, 1);
        mbar_init(sbase + 8, 1);
        mbar_init(sbase + 16, 1);
        mbar_init(sbase + 24, 8);
        mbar_init(sbase + 32, 8);
        mbar_init(sbase + 40, 8);
    }
    __syncthreads();

    auto issue = [&](int g) {
        const int s = g % 3;
        const int k = g / 3;
        if (k >= 1) mbar_wait(sbase + 24u + (uint32_t)s * 8u, (uint32_t)((k - 1) & 1));
        const uint32_t st  = sbase + 1024u + (uint32_t)s * STAGE;
        const uint32_t bar = sbase + (uint32_t)s * 8u;
        const int tile = blockIdx.x + (g >> 4) * PGRID;
        const int c = g & 15;
        mbar_expect_tx(bar, STAGE);
        const size_t atile = ((size_t)((tile >> 3) * 16 + c)) << 14;
        const size_t btile = ((size_t)((tile & 7) * 16 + c)) << 14;
        bulk_g2s(st + AHI_OFF, reinterpret_cast<const char*>(Ahi) + atile, 16384u, bar);
        bulk_g2s(st + ALO_OFF, reinterpret_cast<const char*>(Alo) + atile, 16384u, bar);
        bulk_g2s(st + BHI_OFF, reinterpret_cast<const char*>(Bhi) + btile, 16384u, bar);
        bulk_g2s(st + BLO_OFF, reinterpret_cast<const char*>(Blo) + btile, 16384u, bar);
    };

    float acc1[4][4][4], acc2[4][4][4];
    #pragma unroll
    for (int i = 0; i < 4; i++)
        #pragma unroll
        for (int j = 0; j < 4; j++)
            #pragma unroll
            for (int r = 0; r < 4; r++) { acc1[i][j][r] = 0.0f; acc2[i][j][r] = 0.0f; }

    if (tid == 0) { issue(0); if (G > 1) issue(1); }

    #pragma unroll 1
    for (int g = 0; g < G; g++) {
        if (tid == 0 && g + 2 < G) issue(g + 2);
        mbar_wait(sbase + (uint32_t)(g % 3) * 8u, (uint32_t)((g / 3) & 1));

        const uint32_t st = sbase + 1024u + (uint32_t)(g % 3) * STAGE;
        #pragma unroll
        for (int ks = 0; ks < 4; ks++) {
            uint32_t ah[4][4], al[4][4], bh[4][2], bl[4][2];
            #pragma unroll
            for (int i = 0; i < 4; i++) {
                int row = wm + i * 16 + (lane & 15);
                int ch = 2 * ks + (lane >> 4);
                uint32_t off = (uint32_t)(row * 128) +
                               (uint32_t)(((ch ^ (row & 7)) << 4));
                ldsm_x4(ah[i], st + AHI_OFF + off);
                ldsm_x4(al[i], st + ALO_OFF + off);
            }
            #pragma unroll
            for (int jj = 0; jj < 2; jj++) {
                int row = wn + jj * 16 + ((lane >> 4) << 3) + (lane & 7);
                int ch = 2 * ks + ((lane >> 3) & 1);
                uint32_t off = (uint32_t)(row * 128) +
                               (uint32_t)(((ch ^ (row & 7)) << 4));
                uint32_t t[4];
                ldsm_x4(t, st + BHI_OFF + off);
                bh[2 * jj][0] = t[0]; bh[2 * jj][1] = t[1];
                bh[2 * jj + 1][0] = t[2]; bh[2 * jj + 1][1] = t[3];
                ldsm_x4(t, st + BLO_OFF + off);
                bl[2 * jj][0] = t[0]; bl[2 * jj][1] = t[1];
                bl[2 * jj + 1][0] = t[2]; bl[2 * jj + 1][1] = t[3];
            }
            #pragma unroll
            for (int i = 0; i < 4; i++)
                #pragma unroll
                for (int j = 0; j < 4; j++) {
                    mma_f16(acc1[i][j], ah[i], bh[j]);
                    mma_f16(acc2[i][j], al[i], bh[j]);
                    mma_f16(acc2[i][j], ah[i], bl[j]);
                }
        }

        if (lane == 0) mbar_arrive(sbase + 24u + (uint32_t)(g % 3) * 8u);

        if ((g & 15) == 15) {
            const int tile = blockIdx.x + (g >> 4) * PGRID;
            const int m0 = (tile >> 3) << 7;
            const int n0 = (tile & 7) << 7;
            #pragma unroll
            for (int i = 0; i < 4; i++) {
                int row = m0 + wm + i * 16 + (lane >> 2);
                #pragma unroll
                for (int j = 0; j < 4; j++) {
                    int col = n0 + wn + j * 8 + (lane & 3) * 2;
                    float b0 = __ldg(bias + col);
                    float b1 = __ldg(bias + col + 1);
                    float2 v0, v1;
                    v0.x = fmaf(acc2[i][j][0], LO_INV, acc1[i][j][0]) + b0;
                    v0.y = fmaf(acc2[i][j][1], LO_INV, acc1[i][j][1]) + b1;
                    v1.x = fmaf(acc2[i][j][2], LO_INV, acc1[i][j][2]) + b0;
                    v1.y = fmaf(acc2[i][j][3], LO_INV, acc1[i][j][3]) + b1;
                    *reinterpret_cast<float2*>(&fout[(size_t)row * 1024 + col]) = v0;
                    *reinterpret_cast<float2*>(&fout[(size_t)(row + 8) * 1024 + col]) = v1;
                    acc1[i][j][0] = 0.0f; acc1[i][j][1] = 0.0f;
                    acc1[i][j][2] = 0.0f; acc1[i][j][3] = 0.0f;
                    acc2[i][j][0] = 0.0f; acc2[i][j][1] = 0.0f;
                    acc2[i][j][2] = 0.0f; acc2[i][j][3] = 0.0f;
                }
            }
        }
    }
}

// ---------------------------------------------------------------------------
// SEGMENTED LIF scan: 8 segments of 128 steps, 32-step decay warm-up.
// cp.async TRIPLE-buffered smem staging with 3-deep prefetch (wait_group 2):
// 768 B/thread in flight. Buffer k%3 is reused by batch k+3, issued only
// after batch k is consumed. Same arithmetic order.
// ---------------------------------------------------------------------------
__global__ __launch_bounds__(64)
void lif_kernel(const float* __restrict__ h2, float* __restrict__ pooled8)
{
    __shared__ __align__(16) float4 buf[3][16][64];   // 48 KB
    const int tid = threadIdx.x;
    int idx = blockIdx.x * 64 + tid;            // 0..65535
    int seg = idx >> 13;                        // 0..7
    int col = idx & 8191;
    int b = col >> 8;
    int g4 = col & 255;
    const float4* p = reinterpret_cast<const float4*>(h2 + ((size_t)b << 20)) + g4;

    const int t_start = seg << 7;
    const int warm = (seg > 0) ? 32 : 0;
    const int t_first = t_start - warm;
    const int nbatch = (128 + warm) >> 4;       // 8 or 10

    const uint32_t sbuf = smem_u32(&buf[0][0][tid]);
    auto issue_batch = [&](int k) {
        const float4* src = p + (size_t)(t_first + k * 16) * 256;
        uint32_t dst = sbuf + (uint32_t)(k % 3) * 16384u;
        #pragma unroll
        for (int i = 0; i < 16; i++)
            cp16(dst + (uint32_t)i * 1024u, src + (size_t)i * 256);
        cp_commit();
    };

    issue_batch(0);
    issue_batch(1);
    issue_batch(2);

    float v[4] = {0, 0, 0, 0}, acc[4] = {0, 0, 0, 0};
    const int warm_batches = warm >> 4;          // 0 or 2

    #pragma unroll 1
    for (int k = 0; k < nbatch; k++) {
        if (k + 2 < nbatch)      cp_wait<2>();
        else if (k + 1 < nbatch) cp_wait<1>();
        else                     cp_wait<0>();
        const float4* bk = &buf[k % 3][0][tid];
        if (k < warm_batches) {
            #pragma unroll
            for (int i = 0; i < 16; i++) {
                float4 xv = bk[i * 64];
                float xs[4] = {xv.x, xv.y, xv.z, xv.w};
                #pragma unroll
                for (int c = 0; c < 4; c++) {
                    v[c] = __fadd_rn(v[c], __fmul_rn(__fsub_rn(xs[c], v[c]), 0.5f));
                    if (v[c] >= 1.0f) v[c] = __fsub_rn(v[c], 1.0f);
                }
            }
        } else {
            #pragma unroll
            for (int i = 0; i < 16; i++) {
                float4 xv = bk[i * 64];
                float xs[4] = {xv.x, xv.y, xv.z, xv.w};
                #pragma unroll
                for (int c = 0; c < 4; c++) {
                    v[c] = __fadd_rn(v[c], __fmul_rn(__fsub_rn(xs[c], v[c]), 0.5f));
                    if (v[c] >= 1.0f) { acc[c] += 1.0f; v[c] = __fsub_rn(v[c], 1.0f); }
                }
            }
        }
        if (k + 3 < nbatch) issue_batch(k + 3);
    }

    float4 r;
    r.x = acc[0] * (1.0f / 1024.0f); r.y = acc[1] * (1.0f / 1024.0f);
    r.z = acc[2] * (1.0f / 1024.0f); r.w = acc[3] * (1.0f / 1024.0f);
    reinterpret_cast<float4*>(pooled8)[idx] = r;   // [seg][b][g4] layout
}

// ---------------------------------------------------------------------------
// out[b,o] = sum_g (sum_seg pooled8[seg,b,g]) * W_out[o,g] + b_out[o]
// ---------------------------------------------------------------------------
__global__ __launch_bounds__(256)
void head_kernel(const float* __restrict__ pooled8,
                 const float* __restrict__ W_out,
                 const float* __restrict__ b_out,
                 float* __restrict__ out)
{
    int b = blockIdx.x / 10;
    int o = blockIdx.x % 10;
    float s = 0.0f;
    for (int g = threadIdx.x; g < 1024; g += 256) {
        float pv = 0.0f;
        #pragma unroll
        for (int sg = 0; sg < 8; sg++)
            pv += pooled8[sg * 32768 + b * 1024 + g];
        s = fmaf(pv, W_out[o * 1024 + g], s);
    }
    s = block_reduce_sum(s);
    if (threadIdx.x == 0) out[blockIdx.x] = s + b_out[o];
}

// ---------------------------------------------------------------------------
extern "C" void kernel_launch(void* const* d_in, const int* in_sizes, int n_in,
                              void* d_out, int out_size)
{
    (void)in_sizes; (void)n_in; (void)out_size;
    const float* x      = (const float*)d_in[0];
    const float* W_proj = (const float*)d_in[1];
    const float* b_proj = (const float*)d_in[2];
    const float* W_hid  = (const float*)d_in[3];
    const float* b_hid  = (const float*)d_in[4];
    const float* W_out  = (const float*)d_in[5];
    const float* b_out  = (const float*)d_in[6];
    float* out = (float*)d_out;

    float *bcomb, *h2, *pooled8;
    __half *xhi, *xlo, *whi, *wlo, *ahi, *alo, *bthi, *btlo;
    cudaGetSymbolAddress((void**)&bcomb,   g_bcomb);
    cudaGetSymbolAddress((void**)&h2,      g_h2);
    cudaGetSymbolAddress((void**)&pooled8, g_pooled8);
    cudaGetSymbolAddress((void**)&xhi,     g_xhi);
    cudaGetSymbolAddress((void**)&xlo,     g_xlo);
    cudaGetSymbolAddress((void**)&whi,     g_whi);
    cudaGetSymbolAddress((void**)&wlo,     g_wlo);
    cudaGetSymbolAddress((void**)&ahi,     g_ahi);
    cudaGetSymbolAddress((void**)&alo,     g_alo);
    cudaGetSymbolAddress((void**)&bthi,    g_bthi);
    cudaGetSymbolAddress((void**)&btlo,    g_btlo);

    cudaFuncSetAttribute(hmma_gemm_small,
                         cudaFuncAttributeMaxDynamicSharedMemorySize, (int)S_SMEM);
    cudaFuncSetAttribute(hmma_gemm_persistent,
                         cudaFuncAttributeMaxDynamicSharedMemorySize, (int)SMEM_SZ);

    // 1) fused prologue: x split + W_hid split + W_projT split + b_comb
    prep_all_kernel<<<18944, 256>>>(x, W_proj, W_hid, b_proj, b_hid,
                                    xhi, xlo, ahi, alo, bthi, btlo, bcomb);
    // 2) W_comb = W_hid @ W_projT^T, packed split output (128 CTAs)
    hmma_gemm_small<<<dim3(16, 8), 256, S_SMEM>>>(
        ahi, alo, bthi, btlo, whi, wlo);
    // 3) h2 = x @ W_comb^T + b_comb   (persistent, sync-free mainloop)
    hmma_gemm_persistent<<<PGRID, 256, SMEM_SZ>>>(
        xhi, xlo, whi, wlo, bcomb, h2);
    // 4) segmented LIF (8 segments, triple-buffered 3-deep prefetch)
    lif_kernel<<<1024, 64>>>(h2, pooled8);
    // 5) head over summed segments
    head_kernel<<<320, 256>>>(pooled8, W_out, b_out, out);
}

// round 17
// speedup vs baseline: 1.0290x; 1.0239x over previous
#include <cuda_runtime.h>
#include <cuda_fp16.h>
#include <cstdint>
#include <cstddef>

#define DINL __device__ __forceinline__

// ---------------------------------------------------------------------------
// Scratch (device globals; no allocation allowed)
// Packed layout for all fp16 GEMM operands: 16 KB tiles of (128 rows x 64 k),
// row-major over (rowtile, ktile), interior pre-swizzled for ldmatrix.
// ---------------------------------------------------------------------------
__device__ float g_bcomb[1024];
__device__ float g_h2[32u * 1024u * 1024u];     // [B*T, H] fp32 (134 MB)
__device__ float g_pooled8[8 * 32 * 1024];      // per-segment partial pools
__device__ __align__(128) __half g_xhi[32u * 1024u * 1024u];
__device__ __align__(128) __half g_xlo[32u * 1024u * 1024u];
__device__ __align__(128) __half g_whi[1024u * 1024u];
__device__ __align__(128) __half g_wlo[1024u * 1024u];
__device__ __align__(128) __half g_ahi[1024u * 1024u];   // W_hid split
__device__ __align__(128) __half g_alo[1024u * 1024u];
__device__ __align__(128) __half g_bthi[1024u * 1024u];  // W_projT split
__device__ __align__(128) __half g_btlo[1024u * 1024u];

// Residual scale: lo' = (x - hi) * 2^12, combined as acc1 + acc2 * 2^-12.
static constexpr float LO_SCALE = 4096.0f;
static constexpr float LO_INV   = 1.0f / 4096.0f;

// ---------------------------------------------------------------------------
// PTX helpers (compute_103 baseline-safe)
// ---------------------------------------------------------------------------
DINL uint32_t smem_u32(const void* p) {
    uint32_t r;
    asm("{ .reg .u64 t; cvta.to.shared.u64 t, %1; cvt.u32.u64 %0, t; }"
        : "=r"(r) : "l"(p));
    return r;
}
DINL void cp16(uint32_t dst, const void* src) {
    asm volatile("cp.async.cg.shared.global [%0], [%1], 16;"
                 :: "r"(dst), "l"(src) : "memory");
}
DINL void cp_commit() { asm volatile("cp.async.commit_group;" ::: "memory"); }
template <int N> DINL void cp_wait() {
    asm volatile("cp.async.wait_group %0;" :: "n"(N) : "memory");
}
DINL void ldsm_x4(uint32_t* r, uint32_t addr) {
    asm volatile("ldmatrix.sync.aligned.m8n8.x4.shared.b16 {%0,%1,%2,%3}, [%4];"
                 : "=r"(r[0]), "=r"(r[1]), "=r"(r[2]), "=r"(r[3]) : "r"(addr));
}
DINL void mma_f16(float* d, const uint32_t* a, const uint32_t* b) {
    asm volatile(
        "mma.sync.aligned.m16n8k16.row.col.f32.f16.f16.f32 "
        "{%0,%1,%2,%3}, {%4,%5,%6,%7}, {%8,%9}, {%0,%1,%2,%3};"
        : "+f"(d[0]), "+f"(d[1]), "+f"(d[2]), "+f"(d[3])
        : "r"(a[0]), "r"(a[1]), "r"(a[2]), "r"(a[3]), "r"(b[0]), "r"(b[1]));
}
DINL void mbar_init(uint32_t addr, uint32_t cnt) {
    asm volatile("mbarrier.init.shared.b64 [%0], %1;" :: "r"(addr), "r"(cnt) : "memory");
}
DINL void mbar_expect_tx(uint32_t addr, uint32_t bytes) {
    asm volatile("mbarrier.arrive.expect_tx.shared.b64 _, [%0], %1;"
                 :: "r"(addr), "r"(bytes) : "memory");
}
DINL void mbar_arrive(uint32_t addr) {
    asm volatile("mbarrier.arrive.shared.b64 _, [%0];" :: "r"(addr) : "memory");
}
DINL void mbar_wait(uint32_t addr, uint32_t parity) {
    asm volatile(
        "{\n\t.reg .pred P;\n"
        "W1_%=:\n\tmbarrier.try_wait.parity.acquire.cta.shared::cta.b64 P, [%0], %1, 0x989680;\n\t"
        "@P bra W2_%=;\n\tbra W1_%=;\nW2_%=:\n\t}"
        :: "r"(addr), "r"(parity) : "memory");
}
// 1D bulk async copy global->smem, completion via mbarrier complete_tx.
DINL void bulk_g2s(uint32_t dst, const void* src, uint32_t bytes, uint32_t bar) {
    asm volatile(
        "cp.async.bulk.shared::cluster.global.mbarrier::complete_tx::bytes "
        "[%0], [%1], %2, [%3];"
        :: "r"(dst), "l"(src), "r"(bytes), "r"(bar) : "memory");
}

// Packed-tile byte offset of the 16B group holding (row, k..k+7).
DINL uint32_t pack_off16(uint32_t row, uint32_t k) {
    uint32_t tile  = (row >> 7) * 16u + (k >> 6);
    uint32_t local = (row & 127u) * 128u + ((k >> 3) & 7u) * 16u;
    local ^= (local >> 3) & 0x70u;           // SW128 swizzle
    return tile * 16384u + local;
}

// Split 8 fp32 values -> packed fp16 hi / scaled-lo words.
DINL void split8(const float* f, uint32_t* hw, uint32_t* lw) {
    #pragma unroll
    for (int j = 0; j < 4; j++) {
        __half h0 = __float2half_rn(f[2 * j + 0]);
        __half h1 = __float2half_rn(f[2 * j + 1]);
        __half l0 = __float2half_rn((f[2 * j + 0] - __half2float(h0)) * LO_SCALE);
        __half l1 = __float2half_rn((f[2 * j + 1] - __half2float(h1)) * LO_SCALE);
        unsigned short uh0 = *reinterpret_cast<unsigned short*>(&h0);
        unsigned short uh1 = *reinterpret_cast<unsigned short*>(&h1);
        unsigned short ul0 = *reinterpret_cast<unsigned short*>(&l0);
        unsigned short ul1 = *reinterpret_cast<unsigned short*>(&l1);
        hw[j] = (uint32_t)uh0 | ((uint32_t)uh1 << 16);
        lw[j] = (uint32_t)ul0 | ((uint32_t)ul1 << 16);
    }
}

// ---------------------------------------------------------------------------
// Block reduction helper (256 threads)
// ---------------------------------------------------------------------------
DINL float block_reduce_sum(float v) {
    __shared__ float sh[8];
    int lane = threadIdx.x & 31;
    int w = threadIdx.x >> 5;
    #pragma unroll
    for (int o = 16; o > 0; o >>= 1) v += __shfl_down_sync(0xFFFFFFFFu, v, o);
    if (lane == 0) sh[w] = v;
    __syncthreads();
    if (w == 0) {
        v = (lane < 8) ? sh[lane] : 0.0f;
        #pragma unroll
        for (int o = 4; o > 0; o >>= 1) v += __shfl_down_sync(0xFFFFFFFFu, v, o);
    }
    return v;
}

// ---------------------------------------------------------------------------
// prep_all: fused full prologue (one launch):
//   blocks [0,16384):       x -> packed (xhi, xlo)
//   blocks [16384,16896):   W_hid -> packed (ahi, alo)
//   blocks [16896,17920):   W_projT -> packed (bthi, btlo), transpose fused
//   blocks [17920,18944):   b_comb[g] = W_hid[g,:]@b_proj + b_hid[g]
// ---------------------------------------------------------------------------
__global__ __launch_bounds__(256)
void prep_all_kernel(const float* __restrict__ x,
                     const float* __restrict__ W_proj,
                     const float* __restrict__ W_hid,
                     const float* __restrict__ b_proj,
                     const float* __restrict__ b_hid,
                     __half* __restrict__ xhi, __half* __restrict__ xlo,
                     __half* __restrict__ ahi, __half* __restrict__ alo,
                     __half* __restrict__ bthi, __half* __restrict__ btlo,
                     float* __restrict__ bcomb)
{
    const int tid = threadIdx.x;
    if (blockIdx.x < 16384) {
        uint32_t i = blockIdx.x * 256 + tid;
        uint32_t row = i >> 7;
        uint32_t k = (i & 127u) * 8u;
        const float4* s = reinterpret_cast<const float4*>(x + ((size_t)row << 10) + k);
        float4 a = s[0], b = s[1];
        float f[8] = {a.x, a.y, a.z, a.w, b.x, b.y, b.z, b.w};
        uint32_t hw[4], lw[4];
        split8(f, hw, lw);
        uint32_t off = pack_off16(row, k);
        *reinterpret_cast<uint4*>(reinterpret_cast<char*>(xhi) + off) =
            make_uint4(hw[0], hw[1], hw[2], hw[3]);
        *reinterpret_cast<uint4*>(reinterpret_cast<char*>(xlo) + off) =
            make_uint4(lw[0], lw[1], lw[2], lw[3]);
    } else if (blockIdx.x < 16896) {
        uint32_t i = (blockIdx.x - 16384) * 256 + tid;
        uint32_t row = i >> 7;
        uint32_t k = (i & 127u) * 8u;
        const float4* s = reinterpret_cast<const float4*>(W_hid + ((size_t)row << 10) + k);
        float4 a = s[0], b = s[1];
        float f[8] = {a.x, a.y, a.z, a.w, b.x, b.y, b.z, b.w};
        uint32_t hw[4], lw[4];
        split8(f, hw, lw);
        uint32_t off = pack_off16(row, k);
        *reinterpret_cast<uint4*>(reinterpret_cast<char*>(ahi) + off) =
            make_uint4(hw[0], hw[1], hw[2], hw[3]);
        *reinterpret_cast<uint4*>(reinterpret_cast<char*>(alo) + off) =
            make_uint4(lw[0], lw[1], lw[2], lw[3]);
    } else if (blockIdx.x < 17920) {
        __shared__ float tile[32][33];
        int t = blockIdx.x - 16896;
        int bx = t & 31;           // d-tile
        int by = t >> 5;           // h-tile
        int tx = tid & 31, ty = tid >> 5;   // ty 0..7
        #pragma unroll
        for (int j = 0; j < 32; j += 8)
            tile[ty + j][tx] = W_proj[(size_t)(by * 32 + ty + j) * 1024 + bx * 32 + tx];
        __syncthreads();
        if (tid < 128) {
            int d_local = tid & 31;
            int grp = tid >> 5;              // 0..3 -> h-group of 8
            float f[8];
            #pragma unroll
            for (int e = 0; e < 8; e++) f[e] = tile[grp * 8 + e][d_local];
            uint32_t hw[4], lw[4];
            split8(f, hw, lw);
            uint32_t row = (uint32_t)(bx * 32 + d_local);
            uint32_t k = (uint32_t)(by * 32 + grp * 8);
            uint32_t off = pack_off16(row, k);
            *reinterpret_cast<uint4*>(reinterpret_cast<char*>(bthi) + off) =
                make_uint4(hw[0], hw[1], hw[2], hw[3]);
            *reinterpret_cast<uint4*>(reinterpret_cast<char*>(btlo) + off) =
                make_uint4(lw[0], lw[1], lw[2], lw[3]);
        }
    } else {
        int g = blockIdx.x - 17920;
        float s = 0.0f;
        for (int h = tid; h < 1024; h += 256)
            s = fmaf(W_hid[g * 1024 + h], b_proj[h], s);
        s = block_reduce_sum(s);
        if (tid == 0) bcomb[g] = s + b_hid[g];
    }
}

// ---------------------------------------------------------------------------
// Shared GEMM constants (main persistent GEMM, 128x128 tiles)
// ---------------------------------------------------------------------------
static constexpr uint32_t AHI_OFF = 0u;
static constexpr uint32_t ALO_OFF = 16384u;
static constexpr uint32_t BHI_OFF = 32768u;
static constexpr uint32_t BLO_OFF = 49152u;
static constexpr uint32_t STAGE   = 65536u;
static constexpr uint32_t SMEM_SZ = 1024u + 3u * STAGE;
static constexpr int NCH = 16;                 // K=1024 / 64

// ---------------------------------------------------------------------------
// Small split-precision GEMM for W_comb: 128(M) x 64(N) tiles, grid (16, 8)
// = 128 CTAs. Warp grid 4x2, warp tile 32x32. Empty-barrier ring mainloop.
// Bit-identical wcomb output.
// ---------------------------------------------------------------------------
static constexpr uint32_t S_AHI = 0u;
static constexpr uint32_t S_ALO = 16384u;
static constexpr uint32_t S_BHI = 32768u;       // 8 KB (64 rows)
static constexpr uint32_t S_BLO = 40960u;
static constexpr uint32_t S_STAGE = 49152u;     // 48 KB
static constexpr uint32_t S_SMEM = 1024u + 3u * S_STAGE;

__global__ __launch_bounds__(256, 1)
void hmma_gemm_small(const __half* __restrict__ Ahi, const __half* __restrict__ Alo,
                     const __half* __restrict__ Bhi, const __half* __restrict__ Blo,
                     __half* __restrict__ hi_out, __half* __restrict__ lo_out)
{
    extern __shared__ __align__(1024) char smem[];
    const uint32_t sbase = smem_u32(smem);
    const int tid = threadIdx.x;
    const int wid = tid >> 5;
    const int lane = tid & 31;
    const int wm = (wid >> 1) * 32;      // 4 warp rows x 32
    const int wn = (wid & 1) * 32;       // 2 warp cols x 32
    const int m0 = (int)blockIdx.y << 7; // BM = 128
    const int n0 = (int)blockIdx.x << 6; // BN = 64

    float acc1[2][4][4], acc2[2][4][4];
    #pragma unroll
    for (int i = 0; i < 2; i++)
        #pragma unroll
        for (int j = 0; j < 4; j++)
            #pragma unroll
            for (int r = 0; r < 4; r++) { acc1[i][j][r] = 0.0f; acc2[i][j][r] = 0.0f; }

    if (tid == 0) {
        mbar_init(sbase + 0, 1);
        mbar_init(sbase + 8, 1);
        mbar_init(sbase + 16, 1);
        mbar_init(sbase + 24, 8);
        mbar_init(sbase + 32, 8);
        mbar_init(sbase + 40, 8);
    }
    __syncthreads();

    auto issue = [&](int c) {
        const int s = c % 3;
        const int k = c / 3;
        if (k >= 1) mbar_wait(sbase + 24u + (uint32_t)s * 8u, (uint32_t)((k - 1) & 1));
        const uint32_t st  = sbase + 1024u + (uint32_t)s * S_STAGE;
        const uint32_t bar = sbase + (uint32_t)s * 8u;
        mbar_expect_tx(bar, S_STAGE);
        const size_t atile = ((size_t)(blockIdx.y * 16 + c)) << 14;
        const size_t btile = (((size_t)((n0 >> 7) * 16 + c)) << 14) +
                             (size_t)((n0 & 64) ? 8192 : 0);
        bulk_g2s(st + S_AHI, reinterpret_cast<const char*>(Ahi) + atile, 16384u, bar);
        bulk_g2s(st + S_ALO, reinterpret_cast<const char*>(Alo) + atile, 16384u, bar);
        bulk_g2s(st + S_BHI, reinterpret_cast<const char*>(Bhi) + btile, 8192u, bar);
        bulk_g2s(st + S_BLO, reinterpret_cast<const char*>(Blo) + btile, 8192u, bar);
    };

    if (tid == 0) { issue(0); issue(1); }

    #pragma unroll 1
    for (int c = 0; c < NCH; c++) {
        if (tid == 0 && c + 2 < NCH) issue(c + 2);
        mbar_wait(sbase + (uint32_t)(c % 3) * 8u, (uint32_t)((c / 3) & 1));

        const uint32_t st = sbase + 1024u + (uint32_t)(c % 3) * S_STAGE;
        #pragma unroll
        for (int ks = 0; ks < 4; ks++) {
            uint32_t ah[2][4], al[2][4], bh[4][2], bl[4][2];
            #pragma unroll
            for (int i = 0; i < 2; i++) {
                int row = wm + i * 16 + (lane & 15);
                int ch = 2 * ks + (lane >> 4);
                uint32_t off = (uint32_t)(row * 128) +
                               (uint32_t)(((ch ^ (row & 7)) << 4));
                ldsm_x4(ah[i], st + S_AHI + off);
                ldsm_x4(al[i], st + S_ALO + off);
            }
            #pragma unroll
            for (int jj = 0; jj < 2; jj++) {
                int row = wn + jj * 16 + ((lane >> 4) << 3) + (lane & 7);
                int ch = 2 * ks + ((lane >> 3) & 1);
                uint32_t off = (uint32_t)(row * 128) +
                               (uint32_t)(((ch ^ (row & 7)) << 4));
                uint32_t t[4];
                ldsm_x4(t, st + S_BHI + off);
                bh[2 * jj][0] = t[0]; bh[2 * jj][1] = t[1];
                bh[2 * jj + 1][0] = t[2]; bh[2 * jj + 1][1] = t[3];
                ldsm_x4(t, st + S_BLO + off);
                bl[2 * jj][0] = t[0]; bl[2 * jj][1] = t[1];
                bl[2 * jj + 1][0] = t[2]; bl[2 * jj + 1][1] = t[3];
            }
            #pragma unroll
            for (int i = 0; i < 2; i++)
                #pragma unroll
                for (int j = 0; j < 4; j++) {
                    mma_f16(acc1[i][j], ah[i], bh[j]);
                    mma_f16(acc2[i][j], al[i], bh[j]);
                    mma_f16(acc2[i][j], ah[i], bl[j]);
                }
        }
        if (lane == 0) mbar_arrive(sbase + 24u + (uint32_t)(c % 3) * 8u);
    }
    __syncthreads();

    // Epilogue: combine -> padded smem [128][68] -> packed fp16 split output
    float* stg = reinterpret_cast<float*>(smem + 1024);
    #pragma unroll
    for (int i = 0; i < 2; i++) {
        int row = wm + i * 16 + (lane >> 2);
        #pragma unroll
        for (int j = 0; j < 4; j++) {
            int col = wn + j * 8 + (lane & 3) * 2;
            stg[row * 68 + col]           = fmaf(acc2[i][j][0], LO_INV, acc1[i][j][0]);
            stg[row * 68 + col + 1]       = fmaf(acc2[i][j][1], LO_INV, acc1[i][j][1]);
            stg[(row + 8) * 68 + col]     = fmaf(acc2[i][j][2], LO_INV, acc1[i][j][2]);
            stg[(row + 8) * 68 + col + 1] = fmaf(acc2[i][j][3], LO_INV, acc1[i][j][3]);
        }
    }
    __syncthreads();

    #pragma unroll
    for (int it = 0; it < 4; it++) {
        int g = it * 256 + tid;          // 1024 8-elem groups
        int r = g >> 3;
        int c8 = (g & 7) << 3;
        float4 va = *reinterpret_cast<const float4*>(&stg[r * 68 + c8]);
        float4 vb = *reinterpret_cast<const float4*>(&stg[r * 68 + c8 + 4]);
        float f[8] = {va.x, va.y, va.z, va.w, vb.x, vb.y, vb.z, vb.w};
        uint32_t hw[4], lw[4];
        split8(f, hw, lw);
        uint32_t off = pack_off16((uint32_t)(m0 + r), (uint32_t)(n0 + c8));
        *reinterpret_cast<uint4*>(reinterpret_cast<char*>(hi_out) + off) =
            make_uint4(hw[0], hw[1], hw[2], hw[3]);
        *reinterpret_cast<uint4*>(reinterpret_cast<char*>(lo_out) + off) =
            make_uint4(lw[0], lw[1], lw[2], lw[3]);
    }
}

// ---------------------------------------------------------------------------
// PERSISTENT main GEMM, full/empty mbarrier rings, DISTRIBUTED stage-issue:
// warp s (s in 0..2) owns stage s — its lane 0 waits empty[s] and issues the
// bulk copies. Spreads issue stalls over 3 warps instead of warp 0 alone.
// ---------------------------------------------------------------------------
static constexpr int PGRID = 148;
static constexpr int NTILES = 2048;

__global__ __launch_bounds__(256, 1)
void hmma_gemm_persistent(const __half* __restrict__ Ahi,
                          const __half* __restrict__ Alo,
                          const __half* __restrict__ Bhi,
                          const __half* __restrict__ Blo,
                          const float* __restrict__ bias,
                          float* __restrict__ fout)
{
    extern __shared__ __align__(1024) char smem[];
    const uint32_t sbase = smem_u32(smem);
    const int tid = threadIdx.x;
    const int wid = tid >> 5;
    const int lane = tid & 31;
    const int wm = (wid >> 2) * 64;
    const int wn = (wid & 3) * 32;

    int ntile = 0;
    for (int t = blockIdx.x; t < NTILES; t += PGRID) ntile++;
    const int G = ntile * NCH;

    if (tid == 0) {
        mbar_init(sbase + 0, 1);
        mbar_init(sbase + 8, 1);
        mbar_init(sbase + 16, 1);
        mbar_init(sbase + 24, 8);
        mbar_init(sbase + 32, 8);
        mbar_init(sbase + 40, 8);
    }
    __syncthreads();

    auto issue = [&](int g) {
        const int s = g % 3;
        const int k = g / 3;
        if (k >= 1) mbar_wait(sbase + 24u + (uint32_t)s * 8u, (uint32_t)((k - 1) & 1));
        const uint32_t st  = sbase + 1024u + (uint32_t)s * STAGE;
        const uint32_t bar = sbase + (uint32_t)s * 8u;
        const int tile = blockIdx.x + (g >> 4) * PGRID;
        const int c = g & 15;
        mbar_expect_tx(bar, STAGE);
        const size_t atile = ((size_t)((tile >> 3) * 16 + c)) << 14;
        const size_t btile = ((size_t)((tile & 7) * 16 + c)) << 14;
        bulk_g2s(st + AHI_OFF, reinterpret_cast<const char*>(Ahi) + atile, 16384u, bar);
        bulk_g2s(st + ALO_OFF, reinterpret_cast<const char*>(Alo) + atile, 16384u, bar);
        bulk_g2s(st + BHI_OFF, reinterpret_cast<const char*>(Bhi) + btile, 16384u, bar);
        bulk_g2s(st + BLO_OFF, reinterpret_cast<const char*>(Blo) + btile, 16384u, bar);
    };

    float acc1[4][4][4], acc2[4][4][4];
    #pragma unroll
    for (int i = 0; i < 4; i++)
        #pragma unroll
        for (int j = 0; j < 4; j++)
            #pragma unroll
            for (int r = 0; r < 4; r++) { acc1[i][j][r] = 0.0f; acc2[i][j][r] = 0.0f; }

    // Prologue issues: warp 0 -> chunk 0 (stage 0), warp 1 -> chunk 1 (stage 1).
    if (lane == 0 && wid == 0) issue(0);
    if (lane == 0 && wid == 1 && G > 1) issue(1);

    #pragma unroll 1
    for (int g = 0; g < G; g++) {
        const int gi = g + 2;
        if (gi < G && lane == 0 && wid == (gi % 3)) issue(gi);
        mbar_wait(sbase + (uint32_t)(g % 3) * 8u, (uint32_t)((g / 3) & 1));

        const uint32_t st = sbase + 1024u + (uint32_t)(g % 3) * STAGE;
        #pragma unroll
        for (int ks = 0; ks < 4; ks++) {
            uint32_t ah[4][4], al[4][4], bh[4][2], bl[4][2];
            #pragma unroll
            for (int i = 0; i < 4; i++) {
                int row = wm + i * 16 + (lane & 15);
                int ch = 2 * ks + (lane >> 4);
                uint32_t off = (uint32_t)(row * 128) +
                               (uint32_t)(((ch ^ (row & 7)) << 4));
                ldsm_x4(ah[i], st + AHI_OFF + off);
                ldsm_x4(al[i], st + ALO_OFF + off);
            }
            #pragma unroll
            for (int jj = 0; jj < 2; jj++) {
                int row = wn + jj * 16 + ((lane >> 4) << 3) + (lane & 7);
                int ch = 2 * ks + ((lane >> 3) & 1);
                uint32_t off = (uint32_t)(row * 128) +
                               (uint32_t)(((ch ^ (row & 7)) << 4));
                uint32_t t[4];
                ldsm_x4(t, st + BHI_OFF + off);
                bh[2 * jj][0] = t[0]; bh[2 * jj][1] = t[1];
                bh[2 * jj + 1][0] = t[2]; bh[2 * jj + 1][1] = t[3];
                ldsm_x4(t, st + BLO_OFF + off);
                bl[2 * jj][0] = t[0]; bl[2 * jj][1] = t[1];
                bl[2 * jj + 1][0] = t[2]; bl[2 * jj + 1][1] = t[3];
            }
            #pragma unroll
            for (int i = 0; i < 4; i++)
                #pragma unroll
                for (int j = 0; j < 4; j++) {
                    mma_f16(acc1[i][j], ah[i], bh[j]);
                    mma_f16(acc2[i][j], al[i], bh[j]);
                    mma_f16(acc2[i][j], ah[i], bl[j]);
                }
        }

        if (lane == 0) mbar_arrive(sbase + 24u + (uint32_t)(g % 3) * 8u);

        if ((g & 15) == 15) {
            const int tile = blockIdx.x + (g >> 4) * PGRID;
            const int m0 = (tile >> 3) << 7;
            const int n0 = (tile & 7) << 7;
            #pragma unroll
            for (int i = 0; i < 4; i++) {
                int row = m0 + wm + i * 16 + (lane >> 2);
                #pragma unroll
                for (int j = 0; j < 4; j++) {
                    int col = n0 + wn + j * 8 + (lane & 3) * 2;
                    float b0 = __ldg(bias + col);
                    float b1 = __ldg(bias + col + 1);
                    float2 v0, v1;
                    v0.x = fmaf(acc2[i][j][0], LO_INV, acc1[i][j][0]) + b0;
                    v0.y = fmaf(acc2[i][j][1], LO_INV, acc1[i][j][1]) + b1;
                    v1.x = fmaf(acc2[i][j][2], LO_INV, acc1[i][j][2]) + b0;
                    v1.y = fmaf(acc2[i][j][3], LO_INV, acc1[i][j][3]) + b1;
                    *reinterpret_cast<float2*>(&fout[(size_t)row * 1024 + col]) = v0;
                    *reinterpret_cast<float2*>(&fout[(size_t)(row + 8) * 1024 + col]) = v1;
                    acc1[i][j][0] = 0.0f; acc1[i][j][1] = 0.0f;
                    acc1[i][j][2] = 0.0f; acc1[i][j][3] = 0.0f;
                    acc2[i][j][0] = 0.0f; acc2[i][j][1] = 0.0f;
                    acc2[i][j][2] = 0.0f; acc2[i][j][3] = 0.0f;
                }
            }
        }
    }
}

// ---------------------------------------------------------------------------
// SEGMENTED LIF scan: 8 segments of 128 steps, 32-step decay warm-up.
// cp.async triple-buffered smem staging, 2-deep wait (best measured, R14).
// ---------------------------------------------------------------------------
__global__ __launch_bounds__(64)
void lif_kernel(const float* __restrict__ h2, float* __restrict__ pooled8)
{
    __shared__ __align__(16) float4 buf[3][16][64];   // 48 KB
    const int tid = threadIdx.x;
    int idx = blockIdx.x * 64 + tid;            // 0..65535
    int seg = idx >> 13;                        // 0..7
    int col = idx & 8191;
    int b = col >> 8;
    int g4 = col & 255;
    const float4* p = reinterpret_cast<const float4*>(h2 + ((size_t)b << 20)) + g4;

    const int t_start = seg << 7;
    const int warm = (seg > 0) ? 32 : 0;
    const int t_first = t_start - warm;
    const int nbatch = (128 + warm) >> 4;       // 8 or 10

    const uint32_t sbuf = smem_u32(&buf[0][0][tid]);
    auto issue_batch = [&](int k) {
        const float4* src = p + (size_t)(t_first + k * 16) * 256;
        uint32_t dst = sbuf + (uint32_t)(k % 3) * 16384u;
        #pragma unroll
        for (int i = 0; i < 16; i++)
            cp16(dst + (uint32_t)i * 1024u, src + (size_t)i * 256);
        cp_commit();
    };

    issue_batch(0);
    issue_batch(1);

    float v[4] = {0, 0, 0, 0}, acc[4] = {0, 0, 0, 0};
    const int warm_batches = warm >> 4;          // 0 or 2

    #pragma unroll 1
    for (int k = 0; k < nbatch; k++) {
        if (k + 1 < nbatch) cp_wait<1>(); else cp_wait<0>();
        const float4* bk = &buf[k % 3][0][tid];
        if (k < warm_batches) {
            #pragma unroll
            for (int i = 0; i < 16; i++) {
                float4 xv = bk[i * 64];
                float xs[4] = {xv.x, xv.y, xv.z, xv.w};
                #pragma unroll
                for (int c = 0; c < 4; c++) {
                    v[c] = __fadd_rn(v[c], __fmul_rn(__fsub_rn(xs[c], v[c]), 0.5f));
                    if (v[c] >= 1.0f) v[c] = __fsub_rn(v[c], 1.0f);
                }
            }
        } else {
            #pragma unroll
            for (int i = 0; i < 16; i++) {
                float4 xv = bk[i * 64];
                float xs[4] = {xv.x, xv.y, xv.z, xv.w};
                #pragma unroll
                for (int c = 0; c < 4; c++) {
                    v[c] = __fadd_rn(v[c], __fmul_rn(__fsub_rn(xs[c], v[c]), 0.5f));
                    if (v[c] >= 1.0f) { acc[c] += 1.0f; v[c] = __fsub_rn(v[c], 1.0f); }
                }
            }
        }
        if (k + 2 < nbatch) issue_batch(k + 2);
    }

    float4 r;
    r.x = acc[0] * (1.0f / 1024.0f); r.y = acc[1] * (1.0f / 1024.0f);
    r.z = acc[2] * (1.0f / 1024.0f); r.w = acc[3] * (1.0f / 1024.0f);
    reinterpret_cast<float4*>(pooled8)[idx] = r;   // [seg][b][g4] layout
}

// ---------------------------------------------------------------------------
// out[b,o] = sum_g (sum_seg pooled8[seg,b,g]) * W_out[o,g] + b_out[o]
// ---------------------------------------------------------------------------
__global__ __launch_bounds__(256)
void head_kernel(const float* __restrict__ pooled8,
                 const float* __restrict__ W_out,
                 const float* __restrict__ b_out,
                 float* __restrict__ out)
{
    int b = blockIdx.x / 10;
    int o = blockIdx.x % 10;
    float s = 0.0f;
    for (int g = threadIdx.x; g < 1024; g += 256) {
        float pv = 0.0f;
        #pragma unroll
        for (int sg = 0; sg < 8; sg++)
            pv += pooled8[sg * 32768 + b * 1024 + g];
        s = fmaf(pv, W_out[o * 1024 + g], s);
    }
    s = block_reduce_sum(s);
    if (threadIdx.x == 0) out[blockIdx.x] = s + b_out[o];
}

// ---------------------------------------------------------------------------
extern "C" void kernel_launch(void* const* d_in, const int* in_sizes, int n_in,
                              void* d_out, int out_size)
{
    (void)in_sizes; (void)n_in; (void)out_size;
    const float* x      = (const float*)d_in[0];
    const float* W_proj = (const float*)d_in[1];
    const float* b_proj = (const float*)d_in[2];
    const float* W_hid  = (const float*)d_in[3];
    const float* b_hid  = (const float*)d_in[4];
    const float* W_out  = (const float*)d_in[5];
    const float* b_out  = (const float*)d_in[6];
    float* out = (float*)d_out;

    float *bcomb, *h2, *pooled8;
    __half *xhi, *xlo, *whi, *wlo, *ahi, *alo, *bthi, *btlo;
    cudaGetSymbolAddress((void**)&bcomb,   g_bcomb);
    cudaGetSymbolAddress((void**)&h2,      g_h2);
    cudaGetSymbolAddress((void**)&pooled8, g_pooled8);
    cudaGetSymbolAddress((void**)&xhi,     g_xhi);
    cudaGetSymbolAddress((void**)&xlo,     g_xlo);
    cudaGetSymbolAddress((void**)&whi,     g_whi);
    cudaGetSymbolAddress((void**)&wlo,     g_wlo);
    cudaGetSymbolAddress((void**)&ahi,     g_ahi);
    cudaGetSymbolAddress((void**)&alo,     g_alo);
    cudaGetSymbolAddress((void**)&bthi,    g_bthi);
    cudaGetSymbolAddress((void**)&btlo,    g_btlo);

    cudaFuncSetAttribute(hmma_gemm_small,
                         cudaFuncAttributeMaxDynamicSharedMemorySize, (int)S_SMEM);
    cudaFuncSetAttribute(hmma_gemm_persistent,
                         cudaFuncAttributeMaxDynamicSharedMemorySize, (int)SMEM_SZ);

    // 1) fused prologue: x split + W_hid split + W_projT split + b_comb
    prep_all_kernel<<<18944, 256>>>(x, W_proj, W_hid, b_proj, b_hid,
                                    xhi, xlo, ahi, alo, bthi, btlo, bcomb);
    // 2) W_comb = W_hid @ W_projT^T, packed split output (128 CTAs)
    hmma_gemm_small<<<dim3(16, 8), 256, S_SMEM>>>(
        ahi, alo, bthi, btlo, whi, wlo);
    // 3) h2 = x @ W_comb^T + b_comb   (persistent, distributed-issue)
    hmma_gemm_persistent<<<PGRID, 256, SMEM_SZ>>>(
        xhi, xlo, whi, wlo, bcomb, h2);
    // 4) segmented LIF (8 segments, triple-buffered, 2-deep wait)
    lif_kernel<<<1024, 64>>>(h2, pooled8);
    // 5) head over summed segments
    head_kernel<<<320, 256>>>(pooled8, W_out, b_out, out);
}